// round 16
// baseline (speedup 1.0000x reference)
#include <cuda_runtime.h>

// Problem constants
// B=16, N=1024 (32x32), HEADS=8, DIM_HEAD=64, INNER=512, INP=512, OUP=512
// SCALE = 64^-0.5 = 0.125
// qkv buffer layout: [B*N, 1536] row-major; q cols [0,512), k [512,1024), v [1024,1536)
// head h occupies 64 cols at offset h*64 within each section.

#define BN 16384           // B*N
#define K3 1536            // 3*INNER

// Scratch (static device globals — allowed; no cudaMalloc anywhere)
__device__ float g_qkv[(size_t)BN * K3];                       // ~100.7 MB
__device__ float g_S[(size_t)16 * 8 * 1024 * 1024];            // ~537 MB scores
__device__ float g_att[(size_t)BN * 512];                      // ~33.6 MB

// ---------------------------------------------------------------------------
// Generic SGEMM: C[M,N] = A[M,K] @ B[K,N] (+ bias[N] optional)
// 128x128 block tile, k-step 8, 256 threads, 8x8 per-thread register tile.
// M % 128 == 0, N % 128 == 0, K % 8 == 0 assumed (holds for all our shapes).
// ---------------------------------------------------------------------------
__global__ __launch_bounds__(256) void sgemm128(
    const float* __restrict__ A, const float* __restrict__ Bm,
    float* __restrict__ C, int M, int N, int K,
    const float* __restrict__ bias)
{
    __shared__ float As[8][128];
    __shared__ float Bs[8][128];

    const int tid  = threadIdx.x;
    const int bm   = blockIdx.y * 128;
    const int bn   = blockIdx.x * 128;

    const int arow = tid >> 1;          // 0..127
    const int acol = (tid & 1) * 4;     // 0 or 4
    const int brow = tid >> 5;          // 0..7
    const int bcol = (tid & 31) * 4;    // 0..124

    const int tx = tid & 15;            // col group
    const int ty = tid >> 4;            // row group

    float acc[8][8];
    #pragma unroll
    for (int i = 0; i < 8; i++)
        #pragma unroll
        for (int j = 0; j < 8; j++) acc[i][j] = 0.0f;

    const float* Ap = A  + (size_t)(bm + arow) * K + acol;
    const float* Bp = Bm + (size_t)brow * N + bn + bcol;

    for (int k0 = 0; k0 < K; k0 += 8) {
        float4 av = *(const float4*)(Ap + k0);
        float4 bv = *(const float4*)(Bp + (size_t)k0 * N);

        __syncthreads();   // previous iteration's reads complete before overwrite
        As[acol + 0][arow] = av.x;
        As[acol + 1][arow] = av.y;
        As[acol + 2][arow] = av.z;
        As[acol + 3][arow] = av.w;
        *(float4*)&Bs[brow][bcol] = bv;
        __syncthreads();

        #pragma unroll
        for (int kk = 0; kk < 8; kk++) {
            float a[8], b[8];
            *(float4*)(a)     = *(const float4*)&As[kk][ty * 8];
            *(float4*)(a + 4) = *(const float4*)&As[kk][ty * 8 + 4];
            *(float4*)(b)     = *(const float4*)&Bs[kk][tx * 8];
            *(float4*)(b + 4) = *(const float4*)&Bs[kk][tx * 8 + 4];
            #pragma unroll
            for (int i = 0; i < 8; i++)
                #pragma unroll
                for (int j = 0; j < 8; j++)
                    acc[i][j] += a[i] * b[j];
        }
    }

    float bb[8];
    #pragma unroll
    for (int j = 0; j < 8; j++)
        bb[j] = bias ? bias[bn + tx * 8 + j] : 0.0f;

    #pragma unroll
    for (int i = 0; i < 8; i++) {
        int row = bm + ty * 8 + i;
        float* cp = C + (size_t)row * N + bn + tx * 8;
        float4 o0, o1;
        o0.x = acc[i][0] + bb[0]; o0.y = acc[i][1] + bb[1];
        o0.z = acc[i][2] + bb[2]; o0.w = acc[i][3] + bb[3];
        o1.x = acc[i][4] + bb[4]; o1.y = acc[i][5] + bb[5];
        o1.z = acc[i][6] + bb[6]; o1.w = acc[i][7] + bb[7];
        *(float4*)(cp)     = o0;
        *(float4*)(cp + 4) = o1;
    }
}

// ---------------------------------------------------------------------------
// Scores: per (b,h): S[n,m] = 0.125 * sum_d q[n,d]*k[m,d] + rel_table[rel_index[n*1024+m]][h]
// 64x64 tile, K=64 entirely in smem, 64 threads, 8x8 per thread.
// grid: (m_tiles=16, n_tiles=16, b*8+h=128)
// ---------------------------------------------------------------------------
__global__ __launch_bounds__(64) void scores_kernel(
    const float* __restrict__ qkv, const float* __restrict__ rel_table,
    const int* __restrict__ rel_index, float* __restrict__ S)
{
    __shared__ float Qs[64][65];
    __shared__ float Ks[64][65];

    const int bh = blockIdx.z;
    const int b  = bh >> 3;
    const int h  = bh & 7;
    const int n0 = blockIdx.y * 64;
    const int m0 = blockIdx.x * 64;
    const int tid = threadIdx.x;

    const float* qb = qkv + (size_t)(b * 1024 + n0) * K3 + h * 64;
    const float* kb = qkv + (size_t)(b * 1024 + m0) * K3 + 512 + h * 64;

    #pragma unroll
    for (int i = 0; i < 16; i++) {
        int idx = tid + 64 * i;        // 0..1023
        int row = idx >> 4;            // 0..63
        int c4  = (idx & 15) << 2;     // 0..60
        float4 qv = *(const float4*)(qb + (size_t)row * K3 + c4);
        float4 kv = *(const float4*)(kb + (size_t)row * K3 + c4);
        Qs[row][c4] = qv.x; Qs[row][c4 + 1] = qv.y; Qs[row][c4 + 2] = qv.z; Qs[row][c4 + 3] = qv.w;
        Ks[row][c4] = kv.x; Ks[row][c4 + 1] = kv.y; Ks[row][c4 + 2] = kv.z; Ks[row][c4 + 3] = kv.w;
    }
    __syncthreads();

    const int tx = tid & 7;
    const int ty = tid >> 3;

    float acc[8][8];
    #pragma unroll
    for (int i = 0; i < 8; i++)
        #pragma unroll
        for (int j = 0; j < 8; j++) acc[i][j] = 0.0f;

    #pragma unroll 8
    for (int d = 0; d < 64; d++) {
        float a[8], bb[8];
        #pragma unroll
        for (int i = 0; i < 8; i++) a[i]  = Qs[ty * 8 + i][d];
        #pragma unroll
        for (int j = 0; j < 8; j++) bb[j] = Ks[tx * 8 + j][d];
        #pragma unroll
        for (int i = 0; i < 8; i++)
            #pragma unroll
            for (int j = 0; j < 8; j++)
                acc[i][j] += a[i] * bb[j];
    }

    float* Sb = S + (size_t)bh * 1024 * 1024;
    #pragma unroll
    for (int i = 0; i < 8; i++) {
        int n = n0 + ty * 8 + i;
        const int* ri = rel_index + (size_t)n * 1024 + m0 + tx * 8;
        float* sp = Sb + (size_t)n * 1024 + m0 + tx * 8;
        #pragma unroll
        for (int j = 0; j < 8; j++) {
            sp[j] = acc[i][j] * 0.125f + rel_table[ri[j] * 8 + h];
        }
    }
}

// ---------------------------------------------------------------------------
// Softmax over last axis (1024) — one block per row, 256 threads, float4 each.
// ---------------------------------------------------------------------------
__global__ __launch_bounds__(256) void softmax_kernel(float* __restrict__ S)
{
    __shared__ float red[8];
    const size_t row = blockIdx.x;
    float4* p = (float4*)(S + (row << 10));
    float4 v = p[threadIdx.x];

    float m = fmaxf(fmaxf(v.x, v.y), fmaxf(v.z, v.w));
    #pragma unroll
    for (int o = 16; o > 0; o >>= 1)
        m = fmaxf(m, __shfl_xor_sync(0xffffffffu, m, o));

    const int wid = threadIdx.x >> 5;
    const int lid = threadIdx.x & 31;
    if (lid == 0) red[wid] = m;
    __syncthreads();
    float bm = red[0];
    #pragma unroll
    for (int i = 1; i < 8; i++) bm = fmaxf(bm, red[i]);

    v.x = __expf(v.x - bm);
    v.y = __expf(v.y - bm);
    v.z = __expf(v.z - bm);
    v.w = __expf(v.w - bm);

    float s = v.x + v.y + v.z + v.w;
    #pragma unroll
    for (int o = 16; o > 0; o >>= 1)
        s += __shfl_xor_sync(0xffffffffu, s, o);
    __syncthreads();              // red reuse
    if (lid == 0) red[wid] = s;
    __syncthreads();
    float bs = 0.0f;
    #pragma unroll
    for (int i = 0; i < 8; i++) bs += red[i];

    float inv = __fdividef(1.0f, bs);
    v.x *= inv; v.y *= inv; v.z *= inv; v.w *= inv;
    p[threadIdx.x] = v;
}

// ---------------------------------------------------------------------------
// PV: per (b,h): O[n,d] = sum_m P[n,m] * V[m,d], n-tile 64, d=64 whole, k-step 64
// 64 threads, 8x8 per thread. Output to g_att laid out [b*1024+n, h*64+d].
// grid: (n_tiles=16, 1, bh=128)
// ---------------------------------------------------------------------------
__global__ __launch_bounds__(64) void pv_kernel(
    const float* __restrict__ qkv, const float* __restrict__ S,
    float* __restrict__ att)
{
    __shared__ float Ps[64][65];
    __shared__ float Vs[64][65];

    const int bh = blockIdx.z;
    const int b  = bh >> 3;
    const int h  = bh & 7;
    const int n0 = blockIdx.x * 64;
    const int tid = threadIdx.x;
    const int tx = tid & 7;
    const int ty = tid >> 3;

    float acc[8][8];
    #pragma unroll
    for (int i = 0; i < 8; i++)
        #pragma unroll
        for (int j = 0; j < 8; j++) acc[i][j] = 0.0f;

    const float* Sb = S + ((size_t)bh * 1024 + n0) * 1024;
    const float* vb = qkv + (size_t)b * 1024 * K3 + 1024 + h * 64;

    for (int k0 = 0; k0 < 1024; k0 += 64) {
        __syncthreads();   // protect previous iteration's smem reads
        #pragma unroll
        for (int i = 0; i < 16; i++) {
            int idx = tid + 64 * i;
            int row = idx >> 4;
            int c4  = (idx & 15) << 2;
            float4 pv = *(const float4*)(Sb + (size_t)row * 1024 + k0 + c4);
            float4 vv = *(const float4*)(vb + (size_t)(k0 + row) * K3 + c4);
            Ps[row][c4] = pv.x; Ps[row][c4 + 1] = pv.y; Ps[row][c4 + 2] = pv.z; Ps[row][c4 + 3] = pv.w;
            Vs[row][c4] = vv.x; Vs[row][c4 + 1] = vv.y; Vs[row][c4 + 2] = vv.z; Vs[row][c4 + 3] = vv.w;
        }
        __syncthreads();

        #pragma unroll 8
        for (int kk = 0; kk < 64; kk++) {
            float a[8], bb[8];
            #pragma unroll
            for (int i = 0; i < 8; i++) a[i]  = Ps[ty * 8 + i][kk];
            #pragma unroll
            for (int j = 0; j < 8; j++) bb[j] = Vs[kk][tx * 8 + j];
            #pragma unroll
            for (int i = 0; i < 8; i++)
                #pragma unroll
                for (int j = 0; j < 8; j++)
                    acc[i][j] += a[i] * bb[j];
        }
    }

    #pragma unroll
    for (int i = 0; i < 8; i++) {
        int n = n0 + ty * 8 + i;
        float* op = att + (size_t)(b * 1024 + n) * 512 + h * 64 + tx * 8;
        float4 o0, o1;
        o0.x = acc[i][0]; o0.y = acc[i][1]; o0.z = acc[i][2]; o0.w = acc[i][3];
        o1.x = acc[i][4]; o1.y = acc[i][5]; o1.z = acc[i][6]; o1.w = acc[i][7];
        *(float4*)(op)     = o0;
        *(float4*)(op + 4) = o1;
    }
}

// ---------------------------------------------------------------------------
// launch
// ---------------------------------------------------------------------------
extern "C" void kernel_launch(void* const* d_in, const int* in_sizes, int n_in,
                              void* d_out, int out_size)
{
    const float* x         = (const float*)d_in[0];   // [16,1024,512]
    const float* Wqkv      = (const float*)d_in[1];   // [512,1536]
    const float* rel_table = (const float*)d_in[2];   // [3969,8]
    const float* Wout      = (const float*)d_in[3];   // [512,512]
    const float* bout      = (const float*)d_in[4];   // [512]
    const int*   rel_index = (const int*)d_in[5];     // [1048576]
    float* out = (float*)d_out;                        // [16,1024,512]

    float *qkv, *S, *att;
    cudaGetSymbolAddress((void**)&qkv, g_qkv);
    cudaGetSymbolAddress((void**)&S,   g_S);
    cudaGetSymbolAddress((void**)&att, g_att);

    // 1. QKV projection: [16384,512] @ [512,1536] -> g_qkv
    sgemm128<<<dim3(12, 128), 256>>>(x, Wqkv, qkv, BN, K3, 512, nullptr);

    // 2. Scores + scale + relative-position bias -> g_S [bh,1024,1024]
    scores_kernel<<<dim3(16, 16, 128), 64>>>(qkv, rel_table, rel_index, S);

    // 3. Row softmax in-place
    softmax_kernel<<<16 * 8 * 1024, 256>>>(S);

    // 4. P @ V -> g_att [16384, 512] (head-interleaved layout)
    pv_kernel<<<dim3(16, 1, 128), 64>>>(qkv, S, att);

    // 5. Output projection + bias: [16384,512] @ [512,512] -> out
    sgemm128<<<dim3(4, 128), 256>>>(att, Wout, out, BN, 512, 512, bout);
}

// round 17
// speedup vs baseline: 1.0051x; 1.0051x over previous
#include <cuda_runtime.h>

// Problem constants
// B=16, N=1024 (32x32), HEADS=8, DIM_HEAD=64, INNER=512, INP=512, OUP=512
// SCALE = 64^-0.5 = 0.125
// qkv buffer layout: [B*N, 1536] row-major; q cols [0,512), k [512,1024), v [1024,1536)
// head h occupies 64 cols at offset h*64 within each section.

#define BN 16384           // B*N
#define K3 1536            // 3*INNER

// Scratch (static device globals — allowed; no cudaMalloc anywhere)
__device__ float g_qkv[(size_t)BN * K3];                       // ~100.7 MB
__device__ float g_S[(size_t)16 * 8 * 1024 * 1024];            // ~537 MB scores
__device__ float g_att[(size_t)BN * 512];                      // ~33.6 MB

// ---------------------------------------------------------------------------
// Generic SGEMM: C[M,N] = A[M,K] @ B[K,N] (+ bias[N] optional)
// 128x128 block tile, k-step 8, 256 threads, 8x8 per-thread register tile.
// M % 128 == 0, N % 128 == 0, K % 8 == 0 assumed (holds for all our shapes).
// ---------------------------------------------------------------------------
__global__ __launch_bounds__(256) void sgemm128(
    const float* __restrict__ A, const float* __restrict__ Bm,
    float* __restrict__ C, int M, int N, int K,
    const float* __restrict__ bias)
{
    __shared__ float As[8][128];
    __shared__ float Bs[8][128];

    const int tid  = threadIdx.x;
    const int bm   = blockIdx.y * 128;
    const int bn   = blockIdx.x * 128;

    const int arow = tid >> 1;          // 0..127
    const int acol = (tid & 1) * 4;     // 0 or 4
    const int brow = tid >> 5;          // 0..7
    const int bcol = (tid & 31) * 4;    // 0..124

    const int tx = tid & 15;            // col group
    const int ty = tid >> 4;            // row group

    float acc[8][8];
    #pragma unroll
    for (int i = 0; i < 8; i++)
        #pragma unroll
        for (int j = 0; j < 8; j++) acc[i][j] = 0.0f;

    const float* Ap = A  + (size_t)(bm + arow) * K + acol;
    const float* Bp = Bm + (size_t)brow * N + bn + bcol;

    for (int k0 = 0; k0 < K; k0 += 8) {
        float4 av = *(const float4*)(Ap + k0);
        float4 bv = *(const float4*)(Bp + (size_t)k0 * N);

        __syncthreads();   // previous iteration's reads complete before overwrite
        As[acol + 0][arow] = av.x;
        As[acol + 1][arow] = av.y;
        As[acol + 2][arow] = av.z;
        As[acol + 3][arow] = av.w;
        *(float4*)&Bs[brow][bcol] = bv;
        __syncthreads();

        #pragma unroll
        for (int kk = 0; kk < 8; kk++) {
            float a[8], b[8];
            *(float4*)(a)     = *(const float4*)&As[kk][ty * 8];
            *(float4*)(a + 4) = *(const float4*)&As[kk][ty * 8 + 4];
            *(float4*)(b)     = *(const float4*)&Bs[kk][tx * 8];
            *(float4*)(b + 4) = *(const float4*)&Bs[kk][tx * 8 + 4];
            #pragma unroll
            for (int i = 0; i < 8; i++)
                #pragma unroll
                for (int j = 0; j < 8; j++)
                    acc[i][j] += a[i] * b[j];
        }
    }

    float bb[8];
    #pragma unroll
    for (int j = 0; j < 8; j++)
        bb[j] = bias ? bias[bn + tx * 8 + j] : 0.0f;

    #pragma unroll
    for (int i = 0; i < 8; i++) {
        int row = bm + ty * 8 + i;
        float* cp = C + (size_t)row * N + bn + tx * 8;
        float4 o0, o1;
        o0.x = acc[i][0] + bb[0]; o0.y = acc[i][1] + bb[1];
        o0.z = acc[i][2] + bb[2]; o0.w = acc[i][3] + bb[3];
        o1.x = acc[i][4] + bb[4]; o1.y = acc[i][5] + bb[5];
        o1.z = acc[i][6] + bb[6]; o1.w = acc[i][7] + bb[7];
        *(float4*)(cp)     = o0;
        *(float4*)(cp + 4) = o1;
    }
}

// ---------------------------------------------------------------------------
// Scores: per (b,h): S[n,m] = 0.125 * sum_d q[n,d]*k[m,d] + rel_table[rel_index[n*1024+m]][h]
// 64x64 tile, K=64 entirely in smem, 64 threads, 8x8 per thread.
// grid: (m_tiles=16, n_tiles=16, b*8+h=128)
// ---------------------------------------------------------------------------
__global__ __launch_bounds__(64) void scores_kernel(
    const float* __restrict__ qkv, const float* __restrict__ rel_table,
    const int* __restrict__ rel_index, float* __restrict__ S)
{
    __shared__ float Qs[64][65];
    __shared__ float Ks[64][65];

    const int bh = blockIdx.z;
    const int b  = bh >> 3;
    const int h  = bh & 7;
    const int n0 = blockIdx.y * 64;
    const int m0 = blockIdx.x * 64;
    const int tid = threadIdx.x;

    const float* qb = qkv + (size_t)(b * 1024 + n0) * K3 + h * 64;
    const float* kb = qkv + (size_t)(b * 1024 + m0) * K3 + 512 + h * 64;

    #pragma unroll
    for (int i = 0; i < 16; i++) {
        int idx = tid + 64 * i;        // 0..1023
        int row = idx >> 4;            // 0..63
        int c4  = (idx & 15) << 2;     // 0..60
        float4 qv = *(const float4*)(qb + (size_t)row * K3 + c4);
        float4 kv = *(const float4*)(kb + (size_t)row * K3 + c4);
        Qs[row][c4] = qv.x; Qs[row][c4 + 1] = qv.y; Qs[row][c4 + 2] = qv.z; Qs[row][c4 + 3] = qv.w;
        Ks[row][c4] = kv.x; Ks[row][c4 + 1] = kv.y; Ks[row][c4 + 2] = kv.z; Ks[row][c4 + 3] = kv.w;
    }
    __syncthreads();

    const int tx = tid & 7;
    const int ty = tid >> 3;

    float acc[8][8];
    #pragma unroll
    for (int i = 0; i < 8; i++)
        #pragma unroll
        for (int j = 0; j < 8; j++) acc[i][j] = 0.0f;

    #pragma unroll 8
    for (int d = 0; d < 64; d++) {
        float a[8], bb[8];
        #pragma unroll
        for (int i = 0; i < 8; i++) a[i]  = Qs[ty * 8 + i][d];
        #pragma unroll
        for (int j = 0; j < 8; j++) bb[j] = Ks[tx * 8 + j][d];
        #pragma unroll
        for (int i = 0; i < 8; i++)
            #pragma unroll
            for (int j = 0; j < 8; j++)
                acc[i][j] += a[i] * bb[j];
    }

    float* Sb = S + (size_t)bh * 1024 * 1024;
    #pragma unroll
    for (int i = 0; i < 8; i++) {
        int n = n0 + ty * 8 + i;
        const int* ri = rel_index + (size_t)n * 1024 + m0 + tx * 8;
        float* sp = Sb + (size_t)n * 1024 + m0 + tx * 8;
        #pragma unroll
        for (int j = 0; j < 8; j++) {
            sp[j] = acc[i][j] * 0.125f + rel_table[ri[j] * 8 + h];
        }
    }
}

// ---------------------------------------------------------------------------
// Softmax over last axis (1024) — one block per row, 256 threads, float4 each.
// ---------------------------------------------------------------------------
__global__ __launch_bounds__(256) void softmax_kernel(float* __restrict__ S)
{
    __shared__ float red[8];
    const size_t row = blockIdx.x;
    float4* p = (float4*)(S + (row << 10));
    float4 v = p[threadIdx.x];

    float m = fmaxf(fmaxf(v.x, v.y), fmaxf(v.z, v.w));
    #pragma unroll
    for (int o = 16; o > 0; o >>= 1)
        m = fmaxf(m, __shfl_xor_sync(0xffffffffu, m, o));

    const int wid = threadIdx.x >> 5;
    const int lid = threadIdx.x & 31;
    if (lid == 0) red[wid] = m;
    __syncthreads();
    float bm = red[0];
    #pragma unroll
    for (int i = 1; i < 8; i++) bm = fmaxf(bm, red[i]);

    v.x = __expf(v.x - bm);
    v.y = __expf(v.y - bm);
    v.z = __expf(v.z - bm);
    v.w = __expf(v.w - bm);

    float s = v.x + v.y + v.z + v.w;
    #pragma unroll
    for (int o = 16; o > 0; o >>= 1)
        s += __shfl_xor_sync(0xffffffffu, s, o);
    __syncthreads();              // red reuse
    if (lid == 0) red[wid] = s;
    __syncthreads();
    float bs = 0.0f;
    #pragma unroll
    for (int i = 0; i < 8; i++) bs += red[i];

    float inv = __fdividef(1.0f, bs);
    v.x *= inv; v.y *= inv; v.z *= inv; v.w *= inv;
    p[threadIdx.x] = v;
}

// ---------------------------------------------------------------------------
// PV: per (b,h): O[n,d] = sum_m P[n,m] * V[m,d], n-tile 64, d=64 whole, k-step 64
// 64 threads, 8x8 per thread. Output to g_att laid out [b*1024+n, h*64+d].
// grid: (n_tiles=16, 1, bh=128)
// ---------------------------------------------------------------------------
__global__ __launch_bounds__(64) void pv_kernel(
    const float* __restrict__ qkv, const float* __restrict__ S,
    float* __restrict__ att)
{
    __shared__ float Ps[64][65];
    __shared__ float Vs[64][65];

    const int bh = blockIdx.z;
    const int b  = bh >> 3;
    const int h  = bh & 7;
    const int n0 = blockIdx.x * 64;
    const int tid = threadIdx.x;
    const int tx = tid & 7;
    const int ty = tid >> 3;

    float acc[8][8];
    #pragma unroll
    for (int i = 0; i < 8; i++)
        #pragma unroll
        for (int j = 0; j < 8; j++) acc[i][j] = 0.0f;

    const float* Sb = S + ((size_t)bh * 1024 + n0) * 1024;
    const float* vb = qkv + (size_t)b * 1024 * K3 + 1024 + h * 64;

    for (int k0 = 0; k0 < 1024; k0 += 64) {
        __syncthreads();   // protect previous iteration's smem reads
        #pragma unroll
        for (int i = 0; i < 16; i++) {
            int idx = tid + 64 * i;
            int row = idx >> 4;
            int c4  = (idx & 15) << 2;
            float4 pv = *(const float4*)(Sb + (size_t)row * 1024 + k0 + c4);
            float4 vv = *(const float4*)(vb + (size_t)(k0 + row) * K3 + c4);
            Ps[row][c4] = pv.x; Ps[row][c4 + 1] = pv.y; Ps[row][c4 + 2] = pv.z; Ps[row][c4 + 3] = pv.w;
            Vs[row][c4] = vv.x; Vs[row][c4 + 1] = vv.y; Vs[row][c4 + 2] = vv.z; Vs[row][c4 + 3] = vv.w;
        }
        __syncthreads();

        #pragma unroll 8
        for (int kk = 0; kk < 64; kk++) {
            float a[8], bb[8];
            #pragma unroll
            for (int i = 0; i < 8; i++) a[i]  = Ps[ty * 8 + i][kk];
            #pragma unroll
            for (int j = 0; j < 8; j++) bb[j] = Vs[kk][tx * 8 + j];
            #pragma unroll
            for (int i = 0; i < 8; i++)
                #pragma unroll
                for (int j = 0; j < 8; j++)
                    acc[i][j] += a[i] * bb[j];
        }
    }

    #pragma unroll
    for (int i = 0; i < 8; i++) {
        int n = n0 + ty * 8 + i;
        float* op = att + (size_t)(b * 1024 + n) * 512 + h * 64 + tx * 8;
        float4 o0, o1;
        o0.x = acc[i][0]; o0.y = acc[i][1]; o0.z = acc[i][2]; o0.w = acc[i][3];
        o1.x = acc[i][4]; o1.y = acc[i][5]; o1.z = acc[i][6]; o1.w = acc[i][7];
        *(float4*)(op)     = o0;
        *(float4*)(op + 4) = o1;
    }
}

// ---------------------------------------------------------------------------
// launch
// ---------------------------------------------------------------------------
extern "C" void kernel_launch(void* const* d_in, const int* in_sizes, int n_in,
                              void* d_out, int out_size)
{
    const float* x         = (const float*)d_in[0];   // [16,1024,512]
    const float* Wqkv      = (const float*)d_in[1];   // [512,1536]
    const float* rel_table = (const float*)d_in[2];   // [3969,8]
    const float* Wout      = (const float*)d_in[3];   // [512,512]
    const float* bout      = (const float*)d_in[4];   // [512]
    const int*   rel_index = (const int*)d_in[5];     // [1048576]
    float* out = (float*)d_out;                        // [16,1024,512]

    float *qkv, *S, *att;
    cudaGetSymbolAddress((void**)&qkv, g_qkv);
    cudaGetSymbolAddress((void**)&S,   g_S);
    cudaGetSymbolAddress((void**)&att, g_att);

    // 1. QKV projection: [16384,512] @ [512,1536] -> g_qkv
    sgemm128<<<dim3(12, 128), 256>>>(x, Wqkv, qkv, BN, K3, 512, nullptr);

    // 2. Scores + scale + relative-position bias -> g_S [bh,1024,1024]
    scores_kernel<<<dim3(16, 16, 128), 64>>>(qkv, rel_table, rel_index, S);

    // 3. Row softmax in-place
    softmax_kernel<<<16 * 8 * 1024, 256>>>(S);

    // 4. P @ V -> g_att [16384, 512] (head-interleaved layout)
    pv_kernel<<<dim3(16, 1, 128), 64>>>(qkv, S, att);

    // 5. Output projection + bias: [16384,512] @ [512,512] -> out
    sgemm128<<<dim3(4, 128), 256>>>(att, Wout, out, BN, 512, 512, bout);
}